// round 12
// baseline (speedup 1.0000x reference)
#include <cuda_runtime.h>
#include <math.h>

#define B 8
#define N 256
#define D 128
#define H 256
#define BN (B * N)   // 2048

// Scratch (allocation-free rule: device globals), 16B aligned for vector access
__device__ __align__(16) float g_hi[BN * H];   // slots @ W_m1[:D]
__device__ __align__(16) float g_hj[BN * H];   // slots @ W_m1[D:] + b_m1
__device__ __align__(16) float g_G [BN * H];   // sum_j a_ij * gelu(hi_i + hj_j)
__device__ __align__(16) float g_agg[BN * D];  // G @ W_m2 + asum*b_m2
__device__ __align__(16) float g_u [BN * H];   // update-net hidden (pre/post LN+gelu)
__device__ float g_asum[BN];                   // rowsum(adjacency)

__device__ __forceinline__ float gelu_exact(float x) {
    return 0.5f * x * (1.0f + erff(x * 0.70710678118654752440f));
}

// 2*gelu(x) via the tanh formulation + MUFU tanh.approx (sm_75+)
__device__ __forceinline__ float gelu2_tanh(float x) {
    const float xx = x * x;
    const float inner = fmaf(0.0356774081f, xx, 0.7978845608f);
    const float w = x * inner;
    float t; asm("tanh.approx.f32 %0,%1;" : "=f"(t) : "f"(w));
    return fmaf(x, t, x);                                        // x*(1+t)
}

// ---------------------------------------------------------------------------
// Kernel 0: adjacency row sums. Warp per row.
// ---------------------------------------------------------------------------
__global__ __launch_bounds__(256) void asum_kernel(const float* __restrict__ adj)
{
    const int row  = blockIdx.x * 8 + (threadIdx.x >> 5);  // b*N + n
    const int lane = threadIdx.x & 31;
    const float* arow = adj + (size_t)row * N;
    float s = 0.f;
#pragma unroll
    for (int k = 0; k < 8; ++k) s += arow[lane + k * 32];
#pragma unroll
    for (int o = 16; o > 0; o >>= 1) s += __shfl_xor_sync(~0u, s, o);
    if (lane == 0) g_asum[row] = s;
}

// ---------------------------------------------------------------------------
// Kernel 1: proj GEMM, 64x32 tiles (grid 32x16 = 512 blocks), 256 threads.
// ---------------------------------------------------------------------------
#define KC 32
__global__ __launch_bounds__(256) void proj_kernel(
    const float* __restrict__ slots, const float* __restrict__ W_m1,
    const float* __restrict__ b_m1)
{
    const int r0   = blockIdx.x * 64;
    const int part = blockIdx.y >> 3;        // 0 -> hi, 1 -> hj
    const int c0   = (blockIdx.y & 7) * 32;
    const int tid  = threadIdx.x;
    const int ty   = tid >> 4, tx = tid & 15;

    __shared__ float As[64][KC + 1];
    __shared__ float Ws[KC][33];

    float acc[4][2];
#pragma unroll
    for (int r = 0; r < 4; ++r)
#pragma unroll
        for (int c = 0; c < 2; ++c) acc[r][c] = 0.f;

    const float* wsrc = W_m1 + (size_t)(part * D) * H + c0;

    for (int kc = 0; kc < D; kc += KC) {
#pragma unroll
        for (int l = 0; l < 8; ++l) {
            const int idx = tid + l * 256;
            const int r = idx >> 5, k = idx & 31;
            As[r][k] = slots[(r0 + r) * D + kc + k];
        }
#pragma unroll
        for (int l = 0; l < 4; ++l) {
            const int idx = tid + l * 256;
            const int k = idx >> 5, c = idx & 31;
            Ws[k][c] = wsrc[(kc + k) * H + c];
        }
        __syncthreads();

#pragma unroll
        for (int k = 0; k < KC; ++k) {
            float wv[2], av[4];
#pragma unroll
            for (int c = 0; c < 2; ++c) wv[c] = Ws[k][tx + 16 * c];
#pragma unroll
            for (int r = 0; r < 4; ++r) av[r] = As[ty + 16 * r][k];
#pragma unroll
            for (int r = 0; r < 4; ++r)
#pragma unroll
                for (int c = 0; c < 2; ++c)
                    acc[r][c] = fmaf(av[r], wv[c], acc[r][c]);
        }
        __syncthreads();
    }

    if (part == 0) {
#pragma unroll
        for (int r = 0; r < 4; ++r)
#pragma unroll
            for (int c = 0; c < 2; ++c)
                g_hi[(size_t)(r0 + ty + 16 * r) * H + c0 + tx + 16 * c] = acc[r][c];
    } else {
        float bm[2];
#pragma unroll
        for (int c = 0; c < 2; ++c) bm[c] = b_m1[c0 + tx + 16 * c];
#pragma unroll
        for (int r = 0; r < 4; ++r)
#pragma unroll
            for (int c = 0; c < 2; ++c)
                g_hj[(size_t)(r0 + ty + 16 * r) * H + c0 + tx + 16 * c] = acc[r][c] + bm[c];
    }
}

// ---------------------------------------------------------------------------
// Kernel 2: G[b,i,h] = sum_j a[b,i,j] * gelu(hi[b,i,h] + hjp[b,j,h])
// 2 i-rows per block (grid 1024), 128 threads; thread owns h-pair (2t, 2t+1).
// ---------------------------------------------------------------------------
__global__ __launch_bounds__(128) void msg_agg_kernel(
    const float* __restrict__ adj)
{
    const int row0 = blockIdx.x * 2;
    const int b    = row0 >> 8;
    const int i0   = row0 & (N - 1);
    const int tid  = threadIdx.x;

    __shared__ float a_s[2][N];             // prescaled by 0.5 (gelu2 = 2*gelu)
    const float* adj_b = adj + ((size_t)b * N + i0) * N;
#pragma unroll
    for (int idx = tid; idx < 2 * N; idx += 128)
        ((float*)a_s)[idx] = 0.5f * adj_b[idx];
    __syncthreads();

    const float2* hj2 = (const float2*)(g_hj + (size_t)b * N * H) + tid;
    const float2 hi0 = ((const float2*)(g_hi + (size_t) row0      * H))[tid];
    const float2 hi1 = ((const float2*)(g_hi + (size_t)(row0 + 1) * H))[tid];

    float acc00 = 0.f, acc01 = 0.f, acc10 = 0.f, acc11 = 0.f;

#pragma unroll 4
    for (int j = 0; j < N; ++j) {
        const float2 hj = hj2[(size_t)j * (H / 2)];
        const float a0 = a_s[0][j];
        const float a1 = a_s[1][j];
        acc00 = fmaf(a0, gelu2_tanh(hi0.x + hj.x), acc00);
        acc01 = fmaf(a0, gelu2_tanh(hi0.y + hj.y), acc01);
        acc10 = fmaf(a1, gelu2_tanh(hi1.x + hj.x), acc10);
        acc11 = fmaf(a1, gelu2_tanh(hi1.y + hj.y), acc11);
    }

    float2 o0; o0.x = acc00; o0.y = acc01;
    float2 o1; o1.x = acc10; o1.y = acc11;
    ((float2*)(g_G + (size_t) row0      * H))[tid] = o0;
    ((float2*)(g_G + (size_t)(row0 + 1) * H))[tid] = o1;
}

// ---------------------------------------------------------------------------
// Kernel 3a: agg = G @ W_m2 + asum*b_m2.  64x32 tiles, K=256. Grid (32,4).
// ---------------------------------------------------------------------------
__global__ __launch_bounds__(256) void agg_gemm_kernel(
    const float* __restrict__ W_m2, const float* __restrict__ b_m2)
{
    const int r0  = blockIdx.x * 64;
    const int c0  = blockIdx.y * 32;
    const int tid = threadIdx.x;
    const int ty  = tid >> 4, tx = tid & 15;

    __shared__ float As[64][KC + 1];
    __shared__ float Ws[KC][33];
    __shared__ float asum_s[64];

    if (tid < 64) asum_s[tid] = g_asum[r0 + tid];

    float bm[2];
#pragma unroll
    for (int c = 0; c < 2; ++c) bm[c] = b_m2[c0 + tx + 16 * c];

    float acc[4][2];
#pragma unroll
    for (int r = 0; r < 4; ++r)
#pragma unroll
        for (int c = 0; c < 2; ++c) acc[r][c] = 0.f;

    for (int kc = 0; kc < H; kc += KC) {
#pragma unroll
        for (int l = 0; l < 8; ++l) {
            const int idx = tid + l * 256;
            const int r = idx >> 5, k = idx & 31;
            As[r][k] = g_G[(size_t)(r0 + r) * H + kc + k];
        }
#pragma unroll
        for (int l = 0; l < 4; ++l) {
            const int idx = tid + l * 256;
            const int k = idx >> 5, c = idx & 31;
            Ws[k][c] = W_m2[(size_t)(kc + k) * D + c0 + c];
        }
        __syncthreads();

#pragma unroll
        for (int k = 0; k < KC; ++k) {
            float wv[2], av[4];
#pragma unroll
            for (int c = 0; c < 2; ++c) wv[c] = Ws[k][tx + 16 * c];
#pragma unroll
            for (int r = 0; r < 4; ++r) av[r] = As[ty + 16 * r][k];
#pragma unroll
            for (int r = 0; r < 4; ++r)
#pragma unroll
                for (int c = 0; c < 2; ++c)
                    acc[r][c] = fmaf(av[r], wv[c], acc[r][c]);
        }
        __syncthreads();
    }

#pragma unroll
    for (int r = 0; r < 4; ++r)
#pragma unroll
        for (int c = 0; c < 2; ++c)
            g_agg[(size_t)(r0 + ty + 16 * r) * D + c0 + tx + 16 * c] =
                fmaf(asum_s[ty + 16 * r], bm[c], acc[r][c]);
}

// ---------------------------------------------------------------------------
// Kernel 3b: u = [slots|agg] @ W_u1 + b_u1.  64x32 tiles, K=256. Grid (32,8).
// A-source switches from slots to g_agg at k=128 (KC=32 divides 128).
// ---------------------------------------------------------------------------
__global__ __launch_bounds__(256) void u_gemm_kernel(
    const float* __restrict__ slots,
    const float* __restrict__ W_u1, const float* __restrict__ b_u1)
{
    const int r0  = blockIdx.x * 64;
    const int c0  = blockIdx.y * 32;
    const int tid = threadIdx.x;
    const int ty  = tid >> 4, tx = tid & 15;

    __shared__ float As[64][KC + 1];
    __shared__ float Ws[KC][33];

    float acc[4][2];
#pragma unroll
    for (int r = 0; r < 4; ++r)
#pragma unroll
        for (int c = 0; c < 2; ++c) acc[r][c] = 0.f;

    for (int kc = 0; kc < 2 * D; kc += KC) {
        const float* asrc = (kc < D) ? (slots + kc) : (g_agg + (kc - D));
#pragma unroll
        for (int l = 0; l < 8; ++l) {
            const int idx = tid + l * 256;
            const int r = idx >> 5, k = idx & 31;
            As[r][k] = asrc[(size_t)(r0 + r) * D + k];
        }
#pragma unroll
        for (int l = 0; l < 4; ++l) {
            const int idx = tid + l * 256;
            const int k = idx >> 5, c = idx & 31;
            Ws[k][c] = W_u1[(size_t)(kc + k) * H + c0 + c];
        }
        __syncthreads();

#pragma unroll
        for (int k = 0; k < KC; ++k) {
            float wv[2], av[4];
#pragma unroll
            for (int c = 0; c < 2; ++c) wv[c] = Ws[k][tx + 16 * c];
#pragma unroll
            for (int r = 0; r < 4; ++r) av[r] = As[ty + 16 * r][k];
#pragma unroll
            for (int r = 0; r < 4; ++r)
#pragma unroll
                for (int c = 0; c < 2; ++c)
                    acc[r][c] = fmaf(av[r], wv[c], acc[r][c]);
        }
        __syncthreads();
    }

    float bu[2];
#pragma unroll
    for (int c = 0; c < 2; ++c) bu[c] = b_u1[c0 + tx + 16 * c];
#pragma unroll
    for (int r = 0; r < 4; ++r)
#pragma unroll
        for (int c = 0; c < 2; ++c)
            g_u[(size_t)(r0 + ty + 16 * r) * H + c0 + tx + 16 * c] = acc[r][c] + bu[c];
}

// ---------------------------------------------------------------------------
// Kernel 3c: row-wise LayerNorm + exact gelu, in place on g_u. Warp per row.
// ---------------------------------------------------------------------------
__global__ __launch_bounds__(256) void ln_kernel(
    const float* __restrict__ ln_g, const float* __restrict__ ln_b)
{
    const int row  = blockIdx.x * 8 + (threadIdx.x >> 5);
    const int lane = threadIdx.x & 31;
    float* urow = g_u + (size_t)row * H;

    float v[8];
#pragma unroll
    for (int k = 0; k < 8; ++k) v[k] = urow[lane + k * 32];

    float s = 0.f;
#pragma unroll
    for (int k = 0; k < 8; ++k) s += v[k];
#pragma unroll
    for (int o = 16; o > 0; o >>= 1) s += __shfl_xor_sync(~0u, s, o);
    const float mu = s * (1.f / H);

    float ss = 0.f;
#pragma unroll
    for (int k = 0; k < 8; ++k) { const float d = v[k] - mu; ss += d * d; }
#pragma unroll
    for (int o = 16; o > 0; o >>= 1) ss += __shfl_xor_sync(~0u, ss, o);
    const float rstd = rsqrtf(ss * (1.f / H) + 1e-5f);

#pragma unroll
    for (int k = 0; k < 8; ++k) {
        const int h = lane + k * 32;
        const float x = (v[k] - mu) * rstd * ln_g[h] + ln_b[h];
        urow[h] = gelu_exact(x);
    }
}

// ---------------------------------------------------------------------------
// Kernel 3d: out = slots + u @ W_u2 + b_u2.  64x32 tiles, K=256. Grid (32,4).
// ---------------------------------------------------------------------------
__global__ __launch_bounds__(256) void out_gemm_kernel(
    const float* __restrict__ slots,
    const float* __restrict__ W_u2, const float* __restrict__ b_u2,
    float* __restrict__ out)
{
    const int r0  = blockIdx.x * 64;
    const int c0  = blockIdx.y * 32;
    const int tid = threadIdx.x;
    const int ty  = tid >> 4, tx = tid & 15;

    __shared__ float As[64][KC + 1];
    __shared__ float Ws[KC][33];

    float acc[4][2];
#pragma unroll
    for (int r = 0; r < 4; ++r)
#pragma unroll
        for (int c = 0; c < 2; ++c) acc[r][c] = 0.f;

    for (int kc = 0; kc < H; kc += KC) {
#pragma unroll
        for (int l = 0; l < 8; ++l) {
            const int idx = tid + l * 256;
            const int r = idx >> 5, k = idx & 31;
            As[r][k] = g_u[(size_t)(r0 + r) * H + kc + k];
        }
#pragma unroll
        for (int l = 0; l < 4; ++l) {
            const int idx = tid + l * 256;
            const int k = idx >> 5, c = idx & 31;
            Ws[k][c] = W_u2[(size_t)(kc + k) * D + c0 + c];
        }
        __syncthreads();

#pragma unroll
        for (int k = 0; k < KC; ++k) {
            float wv[2], av[4];
#pragma unroll
            for (int c = 0; c < 2; ++c) wv[c] = Ws[k][tx + 16 * c];
#pragma unroll
            for (int r = 0; r < 4; ++r) av[r] = As[ty + 16 * r][k];
#pragma unroll
            for (int r = 0; r < 4; ++r)
#pragma unroll
                for (int c = 0; c < 2; ++c)
                    acc[r][c] = fmaf(av[r], wv[c], acc[r][c]);
        }
        __syncthreads();
    }

    float bu[2];
#pragma unroll
    for (int c = 0; c < 2; ++c) bu[c] = b_u2[c0 + tx + 16 * c];
#pragma unroll
    for (int r = 0; r < 4; ++r)
#pragma unroll
        for (int c = 0; c < 2; ++c) {
            const size_t o = (size_t)(r0 + ty + 16 * r) * D + c0 + tx + 16 * c;
            out[o] = slots[o] + acc[r][c] + bu[c];
        }
}

// ---------------------------------------------------------------------------
extern "C" void kernel_launch(void* const* d_in, const int* in_sizes, int n_in,
                              void* d_out, int out_size)
{
    const float* slots = (const float*)d_in[0];
    const float* adj   = (const float*)d_in[1];
    const float* W_m1  = (const float*)d_in[2];
    const float* b_m1  = (const float*)d_in[3];
    const float* W_m2  = (const float*)d_in[4];
    const float* b_m2  = (const float*)d_in[5];
    const float* W_u1  = (const float*)d_in[6];
    const float* b_u1  = (const float*)d_in[7];
    const float* ln_g  = (const float*)d_in[8];
    const float* ln_b  = (const float*)d_in[9];
    const float* W_u2  = (const float*)d_in[10];
    const float* b_u2  = (const float*)d_in[11];
    float* out = (float*)d_out;

    asum_kernel<<<BN / 8, 256>>>(adj);
    dim3 pg(BN / 64, 16);
    proj_kernel<<<pg, 256>>>(slots, W_m1, b_m1);
    msg_agg_kernel<<<BN / 2, 128>>>(adj);
    dim3 ag(BN / 64, 4);
    agg_gemm_kernel<<<ag, 256>>>(W_m2, b_m2);
    dim3 ug(BN / 64, 8);
    u_gemm_kernel<<<ug, 256>>>(slots, W_u1, b_u1);
    ln_kernel<<<BN / 8, 256>>>(ln_g, ln_b);
    dim3 og(BN / 64, 4);
    out_gemm_kernel<<<og, 256>>>(slots, W_u2, b_u2, out);
}